// round 1
// baseline (speedup 1.0000x reference)
#include <cuda_runtime.h>

#define BATCH 16
#define T0 64000
#define T1 32000
#define CH1 32
#define T2 16000
#define CH2 64
#define T3 8000
#define CH3 128
#define NH 64
#define NB 64

// -------- scratch (device globals: no allocation allowed) --------
__device__ float g_x1[BATCH * T1 * CH1];      // (b, t, c) layout
__device__ float g_x2[BATCH * T2 * CH2];
__device__ float g_x3[BATCH * T3 * CH3];
__device__ float g_w2t[CH1 * 9 * CH2];        // [(ci*9+k)][c_out]
__device__ float g_w3t[CH2 * 9 * CH3];
__device__ float g_poolpart[BATCH * 50 * CH3];
__device__ float g_amps[BATCH * NH];
__device__ float g_nmag[BATCH * NB];

// -------- weight transpose so conv weight loads are coalesced --------
__global__ void prep_kernel(const float* __restrict__ w2, const float* __restrict__ w3) {
    int tid = blockIdx.x * blockDim.x + threadIdx.x;
    int stride = gridDim.x * blockDim.x;
    for (int i = tid; i < CH2 * CH1 * 9; i += stride) {
        int co = i / (CH1 * 9);
        int r  = i % (CH1 * 9);
        g_w2t[r * CH2 + co] = w2[i];
    }
    for (int i = tid; i < CH3 * CH2 * 9; i += stride) {
        int co = i / (CH2 * 9);
        int r  = i % (CH2 * 9);
        g_w3t[r * CH3 + co] = w3[i];
    }
}

// -------- conv1: (B,1,64000) -> (B,32,32000), stride 2, pad 4, relu --------
__global__ __launch_bounds__(256) void conv1_kernel(const float* __restrict__ audio,
                                                    const float* __restrict__ w1,
                                                    const float* __restrict__ b1) {
    __shared__ float s_a[264];
    int b = blockIdx.y;
    int t0 = blockIdx.x * 128;
    const float* ab = audio + b * T0;
    for (int j = threadIdx.x; j < 263; j += 256) {
        int ti = 2 * t0 - 4 + j;
        s_a[j] = (ti >= 0 && ti < T0) ? ab[ti] : 0.0f;
    }
    __syncthreads();
    int c  = threadIdx.x & 31;
    int tl = threadIdx.x >> 5;   // 0..7
    float w[9];
#pragma unroll
    for (int k = 0; k < 9; k++) w[k] = __ldg(w1 + c * 9 + k);
    float bias = __ldg(b1 + c);
    int tb = tl * 16;
#pragma unroll
    for (int i = 0; i < 16; i++) {
        int tloc = tb + i;
        float acc = bias;
#pragma unroll
        for (int k = 0; k < 9; k++) acc = fmaf(w[k], s_a[2 * tloc + k], acc);
        g_x1[(b * T1 + (t0 + tloc)) * CH1 + c] = fmaxf(acc, 0.0f);
    }
}

// -------- conv2: (B,32,32000) -> (B,64,16000) --------
__global__ __launch_bounds__(256) void conv2_kernel(const float* __restrict__ b2v) {
    __shared__ float s_in[136 * CH1];  // 17.4 KB
    int b  = blockIdx.y;
    int t0 = blockIdx.x * 64;
    for (int idx = threadIdx.x; idx < 136 * CH1; idx += 256) {
        int ti = idx >> 5;
        int ci = idx & 31;
        int tg = 2 * t0 - 4 + ti;
        s_in[idx] = (tg >= 0 && tg < T1) ? g_x1[(b * T1 + tg) * CH1 + ci] : 0.0f;
    }
    __syncthreads();
    int co = threadIdx.x & 63;
    int tg = threadIdx.x >> 6;   // 0..3
    int tb = tg * 16;
    float acc[16];
    float bias = __ldg(b2v + co);
#pragma unroll
    for (int i = 0; i < 16; i++) acc[i] = bias;
    for (int ci = 0; ci < CH1; ci++) {
        float xv[39];
#pragma unroll
        for (int j = 0; j < 39; j++) xv[j] = s_in[(2 * tb + j) * CH1 + ci];
#pragma unroll
        for (int k = 0; k < 9; k++) {
            float w = __ldg(&g_w2t[(ci * 9 + k) * CH2 + co]);
#pragma unroll
            for (int i = 0; i < 16; i++) acc[i] = fmaf(w, xv[2 * i + k], acc[i]);
        }
    }
#pragma unroll
    for (int i = 0; i < 16; i++)
        g_x2[(b * T2 + (t0 + tb + i)) * CH2 + co] = fmaxf(acc[i], 0.0f);
}

// -------- conv3: (B,64,16000) -> (B,128,8000) --------
__global__ __launch_bounds__(256) void conv3_kernel(const float* __restrict__ b3v) {
    __shared__ float s_in[72 * CH2];   // 18.4 KB
    int b  = blockIdx.y;
    int t0 = blockIdx.x * 32;
    for (int idx = threadIdx.x; idx < 72 * CH2; idx += 256) {
        int ti = idx >> 6;
        int ci = idx & 63;
        int tg = 2 * t0 - 4 + ti;
        s_in[idx] = (tg >= 0 && tg < T2) ? g_x2[(b * T2 + tg) * CH2 + ci] : 0.0f;
    }
    __syncthreads();
    int co = threadIdx.x & 127;
    int tg = threadIdx.x >> 7;   // 0..1
    int tb = tg * 16;
    float acc[16];
    float bias = __ldg(b3v + co);
#pragma unroll
    for (int i = 0; i < 16; i++) acc[i] = bias;
    for (int ci = 0; ci < CH2; ci++) {
        float xv[39];
#pragma unroll
        for (int j = 0; j < 39; j++) xv[j] = s_in[(2 * tb + j) * CH2 + ci];
#pragma unroll
        for (int k = 0; k < 9; k++) {
            float w = __ldg(&g_w3t[(ci * 9 + k) * CH3 + co]);
#pragma unroll
            for (int i = 0; i < 16; i++) acc[i] = fmaf(w, xv[2 * i + k], acc[i]);
        }
    }
#pragma unroll
    for (int i = 0; i < 16; i++)
        g_x3[(b * T3 + (t0 + tb + i)) * CH3 + co] = fmaxf(acc[i], 0.0f);
}

// -------- pooling stage A: deterministic partial sums (no atomics) --------
__global__ void poolA_kernel() {
    int b = blockIdx.y;
    int p = blockIdx.x;          // 0..49
    int c = threadIdx.x;         // 0..127
    float s = 0.0f;
    int tstart = p * 160;
    for (int t = tstart; t < tstart + 160; t++)
        s += g_x3[(b * T3 + t) * CH3 + c];
    g_poolpart[(b * 50 + p) * CH3 + c] = s;
}

// -------- head: pooled mean -> linear -> amps normalize / noise mags --------
__global__ void head_kernel(const float* __restrict__ wl, const float* __restrict__ bl) {
    __shared__ float sp[128];
    __shared__ float s_amp[64];
    __shared__ float s_sum;
    int b = blockIdx.x;
    int j = threadIdx.x;   // 0..127
    float s = 0.0f;
    for (int p = 0; p < 50; p++) s += g_poolpart[(b * 50 + p) * CH3 + j];
    sp[j] = s * (1.0f / 8000.0f);
    __syncthreads();
    float dot = __ldg(bl + j);
    for (int c = 0; c < 128; c++) dot = fmaf(sp[c], __ldg(wl + j * 128 + c), dot);
    if (j < 64) s_amp[j] = fmaxf(dot, 0.0f);
    __syncthreads();
    if (j == 0) {
        float t = 0.0f;
        for (int h = 0; h < 64; h++) t += s_amp[h];
        s_sum = t + 1e-6f;
    }
    __syncthreads();
    if (j < 64) g_amps[b * 64 + j] = s_amp[j] / s_sum;
    else        g_nmag[b * 64 + (j - 64)] = dot;
}

// -------- synthesis: harmonic bank + shaped noise --------
// Must match reference fp32 rounding: phase = fl(fl(fl(2pi*f0)*h)*t),
// t[i] = fl(i * fl(4/63999)). Accurate sin of that exact fp32 value.
__global__ __launch_bounds__(256) void synth_kernel(const float* __restrict__ f0,
                                                    const float* __restrict__ wn,
                                                    float* __restrict__ out) {
    __shared__ float s_amps[64];
    __shared__ float s_nm[64];
    int b = blockIdx.y;
    if (threadIdx.x < 64)       s_amps[threadIdx.x]      = g_amps[b * 64 + threadIdx.x];
    else if (threadIdx.x < 128) s_nm[threadIdx.x - 64]   = g_nmag[b * 64 + threadIdx.x - 64];
    __syncthreads();
    int t = blockIdx.x * 256 + threadIdx.x;

    constexpr float DELTA  = 4.0f / 63999.0f;          // fl32, matches jnp.linspace step
    constexpr float TWO_PI = 6.283185307179586f;       // fl32(2*pi)
    float tf  = (float)t * DELTA;
    float a   = TWO_PI * f0[b * T0 + t];

    // Cody-Waite pi/2 split (compile-time exact)
    constexpr double PIO2_D = 1.5707963267948966192313216916397514;
    constexpr float RC1 = (float)PIO2_D;
    constexpr float RC2 = (float)(PIO2_D - (double)RC1);
    constexpr float RC3 = (float)(PIO2_D - (double)RC1 - (double)RC2);
    constexpr float INV_PIO2 = 0.63661977236758134308f;
    const float MAGIC = 12582912.0f;  // 1.5 * 2^23

    float acc = 0.0f;
#pragma unroll
    for (int h = 1; h <= 64; h++) {
        float bh = a * (float)h;     // fl(a*h): matches reference order
        float x  = bh * tf;          // fl(bh*t)
        // x in [0, ~6.5e5]; k = round(x*2/pi) <= 4.1e5 < 2^22 -> magic rint valid
        float kr = fmaf(x, INV_PIO2, MAGIC);
        unsigned q = (unsigned)__float_as_int(kr);
        float kf = kr - MAGIC;
        float r = fmaf(kf, -RC1, x);
        r = fmaf(kf, -RC2, r);
        r = fmaf(kf, -RC3, r);
        float z = r * r;
        // sin poly (cephes)
        float ps = fmaf(-1.9515295891e-4f, z, 8.3321608736e-3f);
        ps = fmaf(ps, z, -1.6666654611e-1f);
        ps = ps * z;
        float sres = fmaf(ps, r, r);
        // cos poly (cephes), full Horner in z
        float pc = fmaf(2.443315711809948e-5f, z, -1.388731625493765e-3f);
        pc = fmaf(pc, z, 4.166664568298827e-2f);
        pc = fmaf(pc, z, -0.5f);
        float cres = fmaf(pc, z, 1.0f);
        // quadrant: q&1 -> cos, q&2 -> negate
        float v = (q & 1u) ? cres : sres;
        v = __int_as_float(__float_as_int(v) ^ (int)((q << 30) & 0x80000000u));
        acc = fmaf(s_amps[h - 1], v, acc);
    }
    int bin = t / 1000;  // 64000 / 64 bins
    float shaped = wn[b * T0 + t] * s_nm[bin];
    out[b * T0 + t] = acc + shaped;
}

extern "C" void kernel_launch(void* const* d_in, const int* in_sizes, int n_in,
                              void* d_out, int out_size) {
    (void)in_sizes; (void)n_in; (void)out_size;
    const float* audio = (const float*)d_in[0];
    const float* f0    = (const float*)d_in[1];
    const float* wn    = (const float*)d_in[2];
    const float* w1    = (const float*)d_in[3];
    const float* b1    = (const float*)d_in[4];
    const float* w2    = (const float*)d_in[5];
    const float* b2    = (const float*)d_in[6];
    const float* w3    = (const float*)d_in[7];
    const float* b3    = (const float*)d_in[8];
    const float* wl    = (const float*)d_in[9];
    const float* bl    = (const float*)d_in[10];
    float* out = (float*)d_out;

    prep_kernel<<<64, 256>>>(w2, w3);
    conv1_kernel<<<dim3(250, 16), 256>>>(audio, w1, b1);
    conv2_kernel<<<dim3(250, 16), 256>>>(b2);
    conv3_kernel<<<dim3(250, 16), 256>>>(b3);
    poolA_kernel<<<dim3(50, 16), 128>>>();
    head_kernel<<<16, 128>>>(wl, bl);
    synth_kernel<<<dim3(250, 16), 256>>>(f0, wn, out);
}

// round 2
// speedup vs baseline: 1.0684x; 1.0684x over previous
#include <cuda_runtime.h>

#define BATCH 16
#define T0 64000
#define T1 32000
#define CH1 32
#define T2 16000
#define CH2 64
#define T3 8000
#define CH3 128
#define NH 64
#define NB 64

// -------- scratch (device globals: no allocation allowed) --------
__device__ float g_x1[BATCH * T1 * CH1];      // (b, t, c) layout
__device__ float g_x2[BATCH * T2 * CH2];
__device__ float g_x3[BATCH * T3 * CH3];
__device__ float g_w2t[CH1 * 9 * CH2];        // [(ci*9+k)][c_out]
__device__ float g_w3t[CH2 * 9 * CH3];
__device__ float g_poolpart[BATCH * 50 * CH3];
__device__ float g_amps[BATCH * NH];
__device__ float g_nmag[BATCH * NB];

// -------- weight transpose so conv weight loads are coalesced --------
__global__ void prep_kernel(const float* __restrict__ w2, const float* __restrict__ w3) {
    int tid = blockIdx.x * blockDim.x + threadIdx.x;
    int stride = gridDim.x * blockDim.x;
    for (int i = tid; i < CH2 * CH1 * 9; i += stride) {
        int co = i / (CH1 * 9);
        int r  = i % (CH1 * 9);
        g_w2t[r * CH2 + co] = w2[i];
    }
    for (int i = tid; i < CH3 * CH2 * 9; i += stride) {
        int co = i / (CH2 * 9);
        int r  = i % (CH2 * 9);
        g_w3t[r * CH3 + co] = w3[i];
    }
}

// -------- conv1: (B,1,64000) -> (B,32,32000), stride 2, pad 4, relu --------
__global__ __launch_bounds__(256) void conv1_kernel(const float* __restrict__ audio,
                                                    const float* __restrict__ w1,
                                                    const float* __restrict__ b1) {
    __shared__ float s_a[264];
    int b = blockIdx.y;
    int t0 = blockIdx.x * 128;
    const float* ab = audio + b * T0;
    for (int j = threadIdx.x; j < 263; j += 256) {
        int ti = 2 * t0 - 4 + j;
        s_a[j] = (ti >= 0 && ti < T0) ? ab[ti] : 0.0f;
    }
    __syncthreads();
    int c  = threadIdx.x & 31;
    int tl = threadIdx.x >> 5;   // 0..7
    float w[9];
#pragma unroll
    for (int k = 0; k < 9; k++) w[k] = __ldg(w1 + c * 9 + k);
    float bias = __ldg(b1 + c);
    int tb = tl * 16;
#pragma unroll
    for (int i = 0; i < 16; i++) {
        int tloc = tb + i;
        float acc = bias;
#pragma unroll
        for (int k = 0; k < 9; k++) acc = fmaf(w[k], s_a[2 * tloc + k], acc);
        g_x1[(b * T1 + (t0 + tloc)) * CH1 + c] = fmaxf(acc, 0.0f);
    }
}

// -------- conv2: (B,32,32000) -> (B,64,16000) --------
// smem tile transposed to (ci, ti) so the per-ci input window is contiguous
// and loadable with LDS.128 (broadcast, conflict-free).
__global__ __launch_bounds__(256) void conv2_kernel(const float* __restrict__ b2v) {
    __shared__ float s_in[CH1 * 136];  // (ci, ti) stride 136 (16B aligned)
    int b  = blockIdx.y;
    int t0 = blockIdx.x * 64;
    for (int idx = threadIdx.x; idx < 136 * CH1; idx += 256) {
        int ti = idx >> 5;          // lane = ci -> coalesced global read
        int ci = idx & 31;
        int tg = 2 * t0 - 4 + ti;
        float v = (tg >= 0 && tg < T1) ? g_x1[(b * T1 + tg) * CH1 + ci] : 0.0f;
        s_in[ci * 136 + ti] = v;    // 8-way store conflict, amortized
    }
    __syncthreads();
    int co = threadIdx.x & 63;
    int tg = threadIdx.x >> 6;   // 0..3
    int tb = tg * 16;
    float acc[16];
    float bias = __ldg(b2v + co);
#pragma unroll
    for (int i = 0; i < 16; i++) acc[i] = bias;
    for (int ci = 0; ci < CH1; ci++) {
        float xv[40];
        const float4* p = reinterpret_cast<const float4*>(&s_in[ci * 136 + 2 * tb]);
#pragma unroll
        for (int m = 0; m < 10; m++) {
            float4 v = p[m];
            xv[4 * m + 0] = v.x; xv[4 * m + 1] = v.y;
            xv[4 * m + 2] = v.z; xv[4 * m + 3] = v.w;
        }
#pragma unroll
        for (int k = 0; k < 9; k++) {
            float w = __ldg(&g_w2t[(ci * 9 + k) * CH2 + co]);
#pragma unroll
            for (int i = 0; i < 16; i++) acc[i] = fmaf(w, xv[2 * i + k], acc[i]);
        }
    }
#pragma unroll
    for (int i = 0; i < 16; i++)
        g_x2[(b * T2 + (t0 + tb + i)) * CH2 + co] = fmaxf(acc[i], 0.0f);
}

// -------- conv3: (B,64,16000) -> (B,128,8000) --------
__global__ __launch_bounds__(256) void conv3_kernel(const float* __restrict__ b3v) {
    __shared__ float s_in[CH2 * 72];   // (ci, ti) stride 72 (16B aligned)
    int b  = blockIdx.y;
    int t0 = blockIdx.x * 32;
    for (int idx = threadIdx.x; idx < 72 * CH2; idx += 256) {
        int ti = idx >> 6;          // lane = ci -> coalesced global read
        int ci = idx & 63;
        int tg = 2 * t0 - 4 + ti;
        float v = (tg >= 0 && tg < T2) ? g_x2[(b * T2 + tg) * CH2 + ci] : 0.0f;
        s_in[ci * 72 + ti] = v;
    }
    __syncthreads();
    int co = threadIdx.x & 127;
    int tg = threadIdx.x >> 7;   // 0..1
    int tb = tg * 16;
    float acc[16];
    float bias = __ldg(b3v + co);
#pragma unroll
    for (int i = 0; i < 16; i++) acc[i] = bias;
    for (int ci = 0; ci < CH2; ci++) {
        float xv[40];
        const float4* p = reinterpret_cast<const float4*>(&s_in[ci * 72 + 2 * tb]);
#pragma unroll
        for (int m = 0; m < 10; m++) {
            float4 v = p[m];
            xv[4 * m + 0] = v.x; xv[4 * m + 1] = v.y;
            xv[4 * m + 2] = v.z; xv[4 * m + 3] = v.w;
        }
#pragma unroll
        for (int k = 0; k < 9; k++) {
            float w = __ldg(&g_w3t[(ci * 9 + k) * CH3 + co]);
#pragma unroll
            for (int i = 0; i < 16; i++) acc[i] = fmaf(w, xv[2 * i + k], acc[i]);
        }
    }
#pragma unroll
    for (int i = 0; i < 16; i++)
        g_x3[(b * T3 + (t0 + tb + i)) * CH3 + co] = fmaxf(acc[i], 0.0f);
}

// -------- pooling stage A: deterministic partial sums (no atomics) --------
__global__ void poolA_kernel() {
    int b = blockIdx.y;
    int p = blockIdx.x;          // 0..49
    int c = threadIdx.x;         // 0..127
    float s = 0.0f;
    int tstart = p * 160;
    for (int t = tstart; t < tstart + 160; t++)
        s += g_x3[(b * T3 + t) * CH3 + c];
    g_poolpart[(b * 50 + p) * CH3 + c] = s;
}

// -------- head: pooled mean -> linear -> amps normalize / noise mags --------
__global__ void head_kernel(const float* __restrict__ wl, const float* __restrict__ bl) {
    __shared__ float sp[128];
    __shared__ float s_amp[64];
    __shared__ float s_sum;
    int b = blockIdx.x;
    int j = threadIdx.x;   // 0..127
    float s = 0.0f;
    for (int p = 0; p < 50; p++) s += g_poolpart[(b * 50 + p) * CH3 + j];
    sp[j] = s * (1.0f / 8000.0f);
    __syncthreads();
    float dot = __ldg(bl + j);
    for (int c = 0; c < 128; c++) dot = fmaf(sp[c], __ldg(wl + j * 128 + c), dot);
    if (j < 64) s_amp[j] = fmaxf(dot, 0.0f);
    __syncthreads();
    if (j == 0) {
        float t = 0.0f;
        for (int h = 0; h < 64; h++) t += s_amp[h];
        s_sum = t + 1e-6f;
    }
    __syncthreads();
    if (j < 64) g_amps[b * 64 + j] = s_amp[j] / s_sum;
    else        g_nmag[b * 64 + (j - 64)] = dot;
}

// -------- synthesis: harmonic bank + shaped noise --------
// Must match reference fp32 rounding: phase = fl(fl(fl(2pi*f0)*h)*t),
// t[i] = fl(i * fl(4/63999)). Accurate sin of that exact fp32 value.
__global__ __launch_bounds__(256) void synth_kernel(const float* __restrict__ f0,
                                                    const float* __restrict__ wn,
                                                    float* __restrict__ out) {
    __shared__ float s_amps[64];
    __shared__ float s_nm[64];
    int b = blockIdx.y;
    if (threadIdx.x < 64)       s_amps[threadIdx.x]      = g_amps[b * 64 + threadIdx.x];
    else if (threadIdx.x < 128) s_nm[threadIdx.x - 64]   = g_nmag[b * 64 + threadIdx.x - 64];
    __syncthreads();
    int t = blockIdx.x * 256 + threadIdx.x;

    constexpr float DELTA  = 4.0f / 63999.0f;          // fl32, matches jnp.linspace step
    constexpr float TWO_PI = 6.283185307179586f;       // fl32(2*pi)
    float tf  = (float)t * DELTA;
    float a   = TWO_PI * f0[b * T0 + t];

    // Cody-Waite pi/2 split (compile-time exact)
    constexpr double PIO2_D = 1.5707963267948966192313216916397514;
    constexpr float RC1 = (float)PIO2_D;
    constexpr float RC2 = (float)(PIO2_D - (double)RC1);
    constexpr float RC3 = (float)(PIO2_D - (double)RC1 - (double)RC2);
    constexpr float INV_PIO2 = 0.63661977236758134308f;
    const float MAGIC = 12582912.0f;  // 1.5 * 2^23

    float acc = 0.0f;
#pragma unroll
    for (int h = 1; h <= 64; h++) {
        float bh = a * (float)h;     // fl(a*h): matches reference order
        float x  = bh * tf;          // fl(bh*t)
        float kr = fmaf(x, INV_PIO2, MAGIC);
        unsigned q = (unsigned)__float_as_int(kr);
        float kf = kr - MAGIC;
        float r = fmaf(kf, -RC1, x);
        r = fmaf(kf, -RC2, r);
        r = fmaf(kf, -RC3, r);
        float z = r * r;
        float ps = fmaf(-1.9515295891e-4f, z, 8.3321608736e-3f);
        ps = fmaf(ps, z, -1.6666654611e-1f);
        ps = ps * z;
        float sres = fmaf(ps, r, r);
        float pc = fmaf(2.443315711809948e-5f, z, -1.388731625493765e-3f);
        pc = fmaf(pc, z, 4.166664568298827e-2f);
        pc = fmaf(pc, z, -0.5f);
        float cres = fmaf(pc, z, 1.0f);
        float v = (q & 1u) ? cres : sres;
        v = __int_as_float(__float_as_int(v) ^ (int)((q << 30) & 0x80000000u));
        acc = fmaf(s_amps[h - 1], v, acc);
    }
    int bin = t / 1000;  // 64000 / 64 bins
    float shaped = wn[b * T0 + t] * s_nm[bin];
    out[b * T0 + t] = acc + shaped;
}

extern "C" void kernel_launch(void* const* d_in, const int* in_sizes, int n_in,
                              void* d_out, int out_size) {
    (void)in_sizes; (void)n_in; (void)out_size;
    const float* audio = (const float*)d_in[0];
    const float* f0    = (const float*)d_in[1];
    const float* wn    = (const float*)d_in[2];
    const float* w1    = (const float*)d_in[3];
    const float* b1    = (const float*)d_in[4];
    const float* w2    = (const float*)d_in[5];
    const float* b2    = (const float*)d_in[6];
    const float* w3    = (const float*)d_in[7];
    const float* b3    = (const float*)d_in[8];
    const float* wl    = (const float*)d_in[9];
    const float* bl    = (const float*)d_in[10];
    float* out = (float*)d_out;

    prep_kernel<<<64, 256>>>(w2, w3);
    conv1_kernel<<<dim3(250, 16), 256>>>(audio, w1, b1);
    conv2_kernel<<<dim3(250, 16), 256>>>(b2);
    conv3_kernel<<<dim3(250, 16), 256>>>(b3);
    poolA_kernel<<<dim3(50, 16), 128>>>();
    head_kernel<<<16, 128>>>(wl, bl);
    synth_kernel<<<dim3(250, 16), 256>>>(f0, wn, out);
}